// round 1
// baseline (speedup 1.0000x reference)
#include <cuda_runtime.h>
#include <math.h>

// Problem constants (guarded by runtime sizes where it matters)
#define NN_MAX 50000
#define S_IN 128
#define S_OUT 128
#define V_IN 16
#define V_OUT 16
#define HID 16
#define SVO 3
#define K_MERGED 153   // S_IN + HID + 3*SVO
#define EPSS 1e-8f

// Scratch (static device globals — no allocation)
__device__ float g_vdf[NN_MAX * 12];     // (N, 3(xyz), 3(SVO)) padded to 12 for float4
__device__ float g_acc[NN_MAX * 16];     // per node: 9 sums (idx c*3+x) + count at [9], padded 16
__device__ float g_WsoT[K_MERGED * 128]; // W_so transposed: [k][o]

// ---------------------------------------------------------------------------
// K1: zero accumulators, compute vdf, transpose W_so
// vdf[n][j][c] = sum_i vector[n][i][j] * W_df[c][i]
// ---------------------------------------------------------------------------
__global__ void k_pre(const float* __restrict__ vector,
                      const float* __restrict__ W_df,
                      const float* __restrict__ W_so,
                      int n_nodes)
{
    int n = blockIdx.x * blockDim.x + threadIdx.x;

    if (n < K_MERGED * 128) {
        int k = n >> 7;
        int o = n & 127;
        g_WsoT[n] = W_so[o * K_MERGED + k];
    }
    if (n >= n_nodes) return;

    // zero accumulators (16 floats)
    float4 z = make_float4(0.f, 0.f, 0.f, 0.f);
    float4* accp = reinterpret_cast<float4*>(g_acc + (size_t)n * 16);
    accp[0] = z; accp[1] = z; accp[2] = z; accp[3] = z;

    // load vector (V_IN,3) = 48 floats, 16B aligned (n*192 bytes)
    float v[48];
    const float4* vp = reinterpret_cast<const float4*>(vector + (size_t)n * 48);
#pragma unroll
    for (int q = 0; q < 12; q++) {
        float4 f = vp[q];
        v[q * 4 + 0] = f.x; v[q * 4 + 1] = f.y;
        v[q * 4 + 2] = f.z; v[q * 4 + 3] = f.w;
    }

#pragma unroll
    for (int j = 0; j < 3; j++) {
        float r0 = 0.f, r1 = 0.f, r2 = 0.f;
#pragma unroll
        for (int i = 0; i < 16; i++) {
            float x = v[i * 3 + j];
            r0 += x * __ldg(&W_df[i]);
            r1 += x * __ldg(&W_df[16 + i]);
            r2 += x * __ldg(&W_df[32 + i]);
        }
        g_vdf[(size_t)n * 12 + j * 3 + 0] = r0;
        g_vdf[(size_t)n * 12 + j * 3 + 1] = r1;
        g_vdf[(size_t)n * 12 + j * 3 + 2] = r2;
    }
}

// ---------------------------------------------------------------------------
// K2: per-edge frame rotation + scatter-add
// local[x][c] = sum_j frames[e][x][j] * vdf[row][j][c]; flat idx = c*3+x
// ---------------------------------------------------------------------------
__global__ void k_edge(const int* __restrict__ ei,
                       const float* __restrict__ frames,
                       int n_edges)
{
    int e = blockIdx.x * blockDim.x + threadIdx.x;
    if (e >= n_edges) return;

    int row = ei[e];  // edge_index[0][e]

    const float4* vp = reinterpret_cast<const float4*>(g_vdf + (size_t)row * 12);
    float4 va = vp[0], vb = vp[1], vc = vp[2];
    float v[9] = { va.x, va.y, va.z, va.w, vb.x, vb.y, vb.z, vb.w, vc.x };

    const float* f = frames + (size_t)e * 9;
    float F[9];
#pragma unroll
    for (int i = 0; i < 9; i++) F[i] = __ldg(&f[i]);

    float loc[9];
#pragma unroll
    for (int x = 0; x < 3; x++) {
#pragma unroll
        for (int c = 0; c < 3; c++) {
            loc[c * 3 + x] = F[x * 3 + 0] * v[0 + c]
                           + F[x * 3 + 1] * v[3 + c]
                           + F[x * 3 + 2] * v[6 + c];
        }
    }

    float* dst = g_acc + (size_t)row * 16;
    asm volatile("red.global.add.v4.f32 [%0], {%1,%2,%3,%4};" ::
                 "l"(dst), "f"(loc[0]), "f"(loc[1]), "f"(loc[2]), "f"(loc[3]) : "memory");
    asm volatile("red.global.add.v4.f32 [%0], {%1,%2,%3,%4};" ::
                 "l"(dst + 4), "f"(loc[4]), "f"(loc[5]), "f"(loc[6]), "f"(loc[7]) : "memory");
    asm volatile("red.global.add.v2.f32 [%0], {%1,%2};" ::
                 "l"(dst + 8), "f"(loc[8]), "f"(1.0f) : "memory");
}

// ---------------------------------------------------------------------------
// K3: node MLP. One block (128 thr) per node iteration; thread t owns output
// column t of W_so, weights resident in registers (coalesced load from g_WsoT).
// ---------------------------------------------------------------------------
__global__ __launch_bounds__(128, 2) void k_post(
    const float* __restrict__ scalar, const float* __restrict__ vector,
    const float* __restrict__ W_down, const float* __restrict__ b_so,
    const float* __restrict__ W_up, const float* __restrict__ W_g,
    const float* __restrict__ b_g,
    float* __restrict__ out_s, float* __restrict__ out_v, int n_nodes)
{
    const int t = threadIdx.x;

    // per-thread W_so column in registers (coalesced: row k, 128 threads)
    float w[K_MERGED];
#pragma unroll
    for (int k = 0; k < K_MERGED; k++) w[k] = g_WsoT[k * 128 + t];
    const float bso = b_so[t];

    __shared__ float sWdown[256], sWup[256], sWg[2048], sbg[16];
    __shared__ float merged[K_MERGED];
    __shared__ float vecs[48], vh[48], ss[128], vr[48], gsig[16];

    if (t < 16) sbg[t] = b_g[t];
#pragma unroll
    for (int i = t; i < 256; i += 128) { sWdown[i] = W_down[i]; sWup[i] = W_up[i]; }
#pragma unroll
    for (int i = t; i < 2048; i += 128) sWg[i] = W_g[i];
    __syncthreads();

    for (int n = blockIdx.x; n < n_nodes; n += gridDim.x) {
        // phase 1: loads
        merged[t] = scalar[(size_t)n * 128 + t];
        if (t < 48) vecs[t] = vector[(size_t)n * 48 + t];
        if (t < 9) {
            float cnt = g_acc[(size_t)n * 16 + 9];
            merged[144 + t] = g_acc[(size_t)n * 16 + t] * (1.0f / fmaxf(cnt, 1.0f));
        }
        __syncthreads();

        // phase 2: vh + vnorm (threads 0..15, one per hidden channel)
        if (t < 16) {
            float a0 = 0.f, a1 = 0.f, a2 = 0.f;
#pragma unroll
            for (int i = 0; i < 16; i++) {
                float wd = sWdown[t * 16 + i];
                a0 += vecs[i * 3 + 0] * wd;
                a1 += vecs[i * 3 + 1] * wd;
                a2 += vecs[i * 3 + 2] * wd;
            }
            vh[0 * 16 + t] = a0;
            vh[1 * 16 + t] = a1;
            vh[2 * 16 + t] = a2;
            merged[128 + t] = sqrtf(a0 * a0 + a1 * a1 + a2 * a2 + EPSS);
        }
        __syncthreads();

        // phase 3: big dot  s[t] = b_so[t] + merged . w
        float s = bso;
#pragma unroll
        for (int k = 0; k < K_MERGED; k++) s += merged[k] * w[k];
        float sig = 1.0f / (1.0f + expf(-s));
        float sil = s * sig;
        out_s[(size_t)n * 128 + t] = sil;
        ss[t] = sil;
        __syncthreads();

        // phase 4: gate partials (all 128 threads) + vrep raw (threads 0..47)
        {
            int o2 = t >> 3, part = t & 7;
            float p = 0.f;
#pragma unroll
            for (int k = 0; k < 16; k++)
                p += ss[part * 16 + k] * sWg[o2 * 128 + part * 16 + k];
            p += __shfl_xor_sync(0xFFFFFFFFu, p, 1);
            p += __shfl_xor_sync(0xFFFFFFFFu, p, 2);
            p += __shfl_xor_sync(0xFFFFFFFFu, p, 4);
            if (part == 0)
                gsig[o2] = 1.0f / (1.0f + expf(-(p + sbg[o2])));
        }
        if (t < 48) {
            int o = t / 3, x = t - o * 3;
            float a = 0.f;
#pragma unroll
            for (int h = 0; h < 16; h++) a += vh[x * 16 + h] * sWup[o * 16 + h];
            vr[t] = a;
        }
        __syncthreads();

        // phase 5: gated vector output  (N, V_OUT, 3)
        if (t < 48) out_v[(size_t)n * 48 + t] = vr[t] * gsig[t / 3];
        __syncthreads();
    }
}

extern "C" void kernel_launch(void* const* d_in, const int* in_sizes, int n_in,
                              void* d_out, int out_size) {
    const float* scalar = (const float*)d_in[0];
    const float* vector = (const float*)d_in[1];
    const int*   ei     = (const int*)d_in[2];
    const float* frames = (const float*)d_in[3];
    // d_in[4] = W_down, d_in[5] = W_df, d_in[6] = W_so, d_in[7] = b_so,
    // d_in[8] = W_up,  d_in[9] = W_g,  d_in[10] = b_g
    const float* W_down = (const float*)d_in[4];
    const float* W_df   = (const float*)d_in[5];
    const float* W_so   = (const float*)d_in[6];
    const float* b_so   = (const float*)d_in[7];
    const float* W_up   = (const float*)d_in[8];
    const float* W_g    = (const float*)d_in[9];
    const float* b_g    = (const float*)d_in[10];

    int n = in_sizes[0] / S_IN;    // nodes
    int e = in_sizes[2] / 2;       // edges

    float* out_s = (float*)d_out;
    float* out_v = out_s + (size_t)n * S_OUT;

    k_pre<<<(n + 255) / 256, 256>>>(vector, W_df, W_so, n);
    k_edge<<<(e + 255) / 256, 256>>>(ei, frames, e);
    k_post<<<296, 128>>>(scalar, vector, W_down, b_so, W_up, W_g, b_g,
                         out_s, out_v, n);
}

// round 2
// speedup vs baseline: 1.8651x; 1.8651x over previous
#include <cuda_runtime.h>
#include <math.h>

#define NN_MAX 50000
#define S_IN 128
#define S_OUT 128
#define V_IN 16
#define V_OUT 16
#define HID 16
#define SVO 3
#define K_MERGED 153
#define EPSS 1e-8f
#define NREP 8

// Scratch (static device globals)
__device__ float g_vdf[NN_MAX * 12];                 // (N,3,3) padded to 12
__device__ float g_acc[NREP * NN_MAX * 16];          // 8 replicas x (9 sums + cnt, pad 16)
__device__ float g_WsoT[K_MERGED * 128];             // W_so transposed [k][o]

// ---------------------------------------------------------------------------
// K1: zero replicated accumulators, compute vdf, transpose W_so
// ---------------------------------------------------------------------------
__global__ void k_pre(const float* __restrict__ vector,
                      const float* __restrict__ W_df,
                      const float* __restrict__ W_so,
                      int n_nodes)
{
    int tid = blockIdx.x * blockDim.x + threadIdx.x;

    int nzero4 = NREP * n_nodes * 4;   // float4 count = NREP*n*16/4
    if (tid < nzero4)
        reinterpret_cast<float4*>(g_acc)[tid] = make_float4(0.f, 0.f, 0.f, 0.f);

    if (tid < K_MERGED * 128) {
        int k = tid >> 7, o = tid & 127;
        g_WsoT[tid] = W_so[o * K_MERGED + k];
    }

    if (tid >= n_nodes) return;
    int n = tid;

    float v[48];
    const float4* vp = reinterpret_cast<const float4*>(vector + (size_t)n * 48);
#pragma unroll
    for (int q = 0; q < 12; q++) {
        float4 f = vp[q];
        v[q*4+0] = f.x; v[q*4+1] = f.y; v[q*4+2] = f.z; v[q*4+3] = f.w;
    }
#pragma unroll
    for (int j = 0; j < 3; j++) {
        float r0 = 0.f, r1 = 0.f, r2 = 0.f;
#pragma unroll
        for (int i = 0; i < 16; i++) {
            float x = v[i*3 + j];
            r0 += x * __ldg(&W_df[i]);
            r1 += x * __ldg(&W_df[16 + i]);
            r2 += x * __ldg(&W_df[32 + i]);
        }
        g_vdf[(size_t)n*12 + j*3 + 0] = r0;
        g_vdf[(size_t)n*12 + j*3 + 1] = r1;
        g_vdf[(size_t)n*12 + j*3 + 2] = r2;
    }
}

// ---------------------------------------------------------------------------
// K2: per-edge rotation + replicated scatter-add (replica = e & 7)
// ---------------------------------------------------------------------------
__global__ void k_edge(const int* __restrict__ ei,
                       const float* __restrict__ frames,
                       int n_edges, int n_nodes)
{
    int e = blockIdx.x * blockDim.x + threadIdx.x;
    if (e >= n_edges) return;

    int row = ei[e];

    const float4* vp = reinterpret_cast<const float4*>(g_vdf + (size_t)row * 12);
    float4 va = vp[0], vb = vp[1], vc = vp[2];
    float v[9] = { va.x, va.y, va.z, va.w, vb.x, vb.y, vb.z, vb.w, vc.x };

    const float* f = frames + (size_t)e * 9;
    float F[9];
#pragma unroll
    for (int i = 0; i < 9; i++) F[i] = __ldg(&f[i]);

    float loc[9];
#pragma unroll
    for (int x = 0; x < 3; x++)
#pragma unroll
        for (int c = 0; c < 3; c++)
            loc[c*3 + x] = F[x*3+0]*v[0+c] + F[x*3+1]*v[3+c] + F[x*3+2]*v[6+c];

    int rep = e & (NREP - 1);
    float* dst = g_acc + ((size_t)rep * n_nodes + row) * 16;
    asm volatile("red.global.add.v4.f32 [%0], {%1,%2,%3,%4};" ::
                 "l"(dst), "f"(loc[0]), "f"(loc[1]), "f"(loc[2]), "f"(loc[3]) : "memory");
    asm volatile("red.global.add.v4.f32 [%0], {%1,%2,%3,%4};" ::
                 "l"(dst+4), "f"(loc[4]), "f"(loc[5]), "f"(loc[6]), "f"(loc[7]) : "memory");
    asm volatile("red.global.add.v2.f32 [%0], {%1,%2};" ::
                 "l"(dst+8), "f"(loc[8]), "f"(1.0f) : "memory");
}

// ---------------------------------------------------------------------------
// K3: node MLP, 4-node tiles, f32x2 packed GEMM, double-buffered scalar.
// merged layout in smem: k-pairs: mbuf[(k>>1)*8 + nd*2 + (k&1)], leftover
// k=152 at mbuf[616+nd]. Buffer size 624 floats.
// ---------------------------------------------------------------------------
__global__ __launch_bounds__(128, 2) void k_post(
    const float* __restrict__ scalar, const float* __restrict__ vector,
    const float* __restrict__ W_down, const float* __restrict__ b_so,
    const float* __restrict__ W_up, const float* __restrict__ W_g,
    const float* __restrict__ b_g,
    float* __restrict__ out_s, float* __restrict__ out_v, int n_nodes)
{
    const int t = threadIdx.x;

    // pre-packed W_so column: 76 k-pairs + leftover
    unsigned long long ww[76];
    float wlast;
#pragma unroll
    for (int kp = 0; kp < 76; kp++) {
        float w0 = g_WsoT[(2*kp)   * 128 + t];
        float w1 = g_WsoT[(2*kp+1) * 128 + t];
        asm("mov.b64 %0, {%1, %2};" : "=l"(ww[kp]) : "f"(w0), "f"(w1));
    }
    wlast = g_WsoT[152 * 128 + t];
    const float bso = b_so[t];

    __shared__ float sWdown[256], sWup[256], sWg[2048], sbg[16];
    __shared__ float mT[2][624];
    __shared__ float vecs[4][48];
    __shared__ float vh[4][48];
    __shared__ float ssm[4][128];
    __shared__ float gsig[4][16];

    if (t < 16) sbg[t] = b_g[t];
#pragma unroll
    for (int i = t; i < 256; i += 128) { sWdown[i] = W_down[i]; sWup[i] = W_up[i]; }
#pragma unroll
    for (int i = t; i < 2048; i += 128) sWg[i] = W_g[i];

    const int ntiles = (n_nodes + 3) >> 2;
    int tile = blockIdx.x;
    int cur = 0;

    // preload first tile's scalar into mT[0]
    if (tile < ntiles) {
        int nb = tile * 4;
#pragma unroll
        for (int nd = 0; nd < 4; nd++) {
            float p = (nb + nd < n_nodes) ? scalar[(size_t)(nb + nd) * 128 + t] : 0.f;
            mT[0][(t >> 1) * 8 + nd * 2 + (t & 1)] = p;
        }
    }

    for (; tile < ntiles; tile += gridDim.x) {
        const int nb = tile * 4;
        float* mbuf = mT[cur];

        // ---- Phase A: vecs + replica-summed scatter-mean ----
        if (t < 48) {
            // 4 nodes x 48 floats = 48 float4
            reinterpret_cast<float4*>(&vecs[0][0])[t] =
                reinterpret_cast<const float4*>(vector + (size_t)nb * 48)[t];
        }
        if (t < 36) {
            int nd = t / 9, c = t - nd * 9;
            int node = nb + nd;
            float sum = 0.f, cnt = 0.f;
            if (node < n_nodes) {
#pragma unroll
                for (int r = 0; r < NREP; r++) {
                    const float* a = g_acc + ((size_t)r * n_nodes + node) * 16;
                    sum += a[c];
                    cnt += a[9];
                }
            }
            float val = sum * (1.0f / fmaxf(cnt, 1.0f));
            int kk = 144 + c;
            if (kk < 152) mbuf[(kk >> 1) * 8 + nd * 2 + (kk & 1)] = val;
            else          mbuf[616 + nd] = val;
        }
        __syncthreads();

        // ---- Phase B: vnorm + vh; prefetch next tile's scalar ----
        if (t < 64) {
            int nd = t >> 4, h = t & 15;
            float a0 = 0.f, a1 = 0.f, a2 = 0.f;
#pragma unroll
            for (int i = 0; i < 16; i++) {
                float wd = sWdown[h * 16 + i];
                a0 += vecs[nd][i*3 + 0] * wd;
                a1 += vecs[nd][i*3 + 1] * wd;
                a2 += vecs[nd][i*3 + 2] * wd;
            }
            vh[nd][0*16 + h] = a0;
            vh[nd][1*16 + h] = a1;
            vh[nd][2*16 + h] = a2;
            int kk = 128 + h;
            mT[cur][(kk >> 1) * 8 + nd * 2 + (kk & 1)] =
                sqrtf(a0*a0 + a1*a1 + a2*a2 + EPSS);
        }
        {
            int ntile = tile + gridDim.x;
            if (ntile < ntiles) {
                int nbn = ntile * 4;
                float* nbuf = mT[cur ^ 1];
#pragma unroll
                for (int nd = 0; nd < 4; nd++) {
                    float p = (nbn + nd < n_nodes) ? scalar[(size_t)(nbn + nd) * 128 + t] : 0.f;
                    nbuf[(t >> 1) * 8 + nd * 2 + (t & 1)] = p;
                }
            }
        }
        __syncthreads();

        // ---- Phase C: packed GEMM (153 x 4 nodes), silu, out_s ----
        {
            unsigned long long acc0 = 0ULL, acc1 = 0ULL, acc2 = 0ULL, acc3 = 0ULL;
#pragma unroll
            for (int kp = 0; kp < 76; kp++) {
                const unsigned long long* m =
                    reinterpret_cast<const unsigned long long*>(mbuf + kp * 8);
                asm("fma.rn.f32x2 %0, %1, %2, %0;" : "+l"(acc0) : "l"(ww[kp]), "l"(m[0]));
                asm("fma.rn.f32x2 %0, %1, %2, %0;" : "+l"(acc1) : "l"(ww[kp]), "l"(m[1]));
                asm("fma.rn.f32x2 %0, %1, %2, %0;" : "+l"(acc2) : "l"(ww[kp]), "l"(m[2]));
                asm("fma.rn.f32x2 %0, %1, %2, %0;" : "+l"(acc3) : "l"(ww[kp]), "l"(m[3]));
            }
            float s[4];
            {
                float lo, hi;
                asm("mov.b64 {%0, %1}, %2;" : "=f"(lo), "=f"(hi) : "l"(acc0));
                s[0] = lo + hi;
                asm("mov.b64 {%0, %1}, %2;" : "=f"(lo), "=f"(hi) : "l"(acc1));
                s[1] = lo + hi;
                asm("mov.b64 {%0, %1}, %2;" : "=f"(lo), "=f"(hi) : "l"(acc2));
                s[2] = lo + hi;
                asm("mov.b64 {%0, %1}, %2;" : "=f"(lo), "=f"(hi) : "l"(acc3));
                s[3] = lo + hi;
            }
#pragma unroll
            for (int nd = 0; nd < 4; nd++) {
                float sv = s[nd] + bso + wlast * mbuf[616 + nd];
                float sil = sv / (1.0f + __expf(-sv));
                ssm[nd][t] = sil;
                if (nb + nd < n_nodes)
                    out_s[(size_t)(nb + nd) * 128 + t] = sil;
            }
        }
        __syncthreads();

        // ---- Phase D: gates then gated vector output ----
        {
            int o2 = t >> 3, part = t & 7;
#pragma unroll
            for (int nd = 0; nd < 4; nd++) {
                float p = 0.f;
#pragma unroll
                for (int k = 0; k < 16; k++)
                    p += ssm[nd][part*16 + k] * sWg[o2*128 + part*16 + k];
                p += __shfl_xor_sync(0xFFFFFFFFu, p, 1);
                p += __shfl_xor_sync(0xFFFFFFFFu, p, 2);
                p += __shfl_xor_sync(0xFFFFFFFFu, p, 4);
                if (part == 0)
                    gsig[nd][o2] = 1.0f / (1.0f + __expf(-(p + sbg[o2])));
            }
        }
        __syncthreads();
        if (t < 48) {
            int o = t / 3, x = t - o * 3;
#pragma unroll
            for (int nd = 0; nd < 4; nd++) {
                float a = 0.f;
#pragma unroll
                for (int h = 0; h < 16; h++)
                    a += vh[nd][x*16 + h] * sWup[o*16 + h];
                if (nb + nd < n_nodes)
                    out_v[(size_t)(nb + nd) * 48 + t] = a * gsig[nd][o];
            }
        }
        __syncthreads();
        cur ^= 1;
    }
}

extern "C" void kernel_launch(void* const* d_in, const int* in_sizes, int n_in,
                              void* d_out, int out_size) {
    const float* scalar = (const float*)d_in[0];
    const float* vector = (const float*)d_in[1];
    const int*   ei     = (const int*)d_in[2];
    const float* frames = (const float*)d_in[3];
    const float* W_down = (const float*)d_in[4];
    const float* W_df   = (const float*)d_in[5];
    const float* W_so   = (const float*)d_in[6];
    const float* b_so   = (const float*)d_in[7];
    const float* W_up   = (const float*)d_in[8];
    const float* W_g    = (const float*)d_in[9];
    const float* b_g    = (const float*)d_in[10];

    int n = in_sizes[0] / S_IN;
    int e = in_sizes[2] / 2;

    float* out_s = (float*)d_out;
    float* out_v = out_s + (size_t)n * S_OUT;

    int pre_jobs = NREP * n * 4;             // zeroing dominates thread count
    if (pre_jobs < n) pre_jobs = n;
    if (pre_jobs < K_MERGED * 128) pre_jobs = K_MERGED * 128;

    k_pre<<<(pre_jobs + 255) / 256, 256>>>(vector, W_df, W_so, n);
    k_edge<<<(e + 255) / 256, 256>>>(ei, frames, e, n);
    k_post<<<296, 128>>>(scalar, vector, W_down, b_so, W_up, W_g, b_g,
                         out_s, out_v, n);
}